// round 1
// baseline (speedup 1.0000x reference)
#include <cuda_runtime.h>
#include <cstdint>

typedef unsigned long long u64;

#define B_    8
#define CM_   64
#define CQ_   64
#define CIN_  128
#define CO_   64
#define H_    128
#define W_    128
#define K_    9
#define JOFF_ 27
#define HW_   (H_*W_)

// Scratch (no cudaMalloc allowed): offset-conv output + transposed deform weights.
__device__ __align__(16) float g_off[B_*JOFF_*HW_];   // [b][j][h][w], j: 0..17 offsets, 18..26 mask
__device__ __align__(16) float g_wt[K_*CM_*CO_];      // [k][c][o]

__device__ __forceinline__ u64 pack2(float lo, float hi) {
    u64 r; asm("mov.b64 %0, {%1,%2};" : "=l"(r) : "f"(lo), "f"(hi)); return r;
}
__device__ __forceinline__ void ffma2(u64 &d, u64 a, u64 b) {
    asm("fma.rn.f32x2 %0, %1, %2, %0;" : "+l"(d) : "l"(a), "l"(b));
}

// ---------------------------------------------------------------------------
// Transpose w_def [o][c][k] -> g_wt [k][c][o] so output channels are contiguous.
// ---------------------------------------------------------------------------
__global__ void transpose_wdef_kernel(const float* __restrict__ w_def) {
    int i = blockIdx.x * 256 + threadIdx.x;
    if (i < K_*CM_*CO_) {
        int k = i / (CM_*CO_);
        int r = i - k*(CM_*CO_);
        int c = r / CO_;
        int o = r - c*CO_;
        g_wt[i] = w_def[(o*CM_ + c)*K_ + k];
    }
}

// ---------------------------------------------------------------------------
// Offset conv: off[b][j][h][w] = b_off[j] + sum_c sum_tap x[c][h+ky-1][w+kx-1] * W[j][c][tap]
// x = concat(mem, que) along channels (128 total).
// Block = one (b,h) row of 128 pixels. 64 threads = 16 pixel-pair slots x 4 j-groups (7 j, pad 28).
// All inner-loop operands are 8B LDS: sh_x2[r][i] = {x[i-1], x[i]}, sh_w2 = {w,w} duplicated.
// ---------------------------------------------------------------------------
__global__ __launch_bounds__(64) void offset_conv_kernel(
        const float* __restrict__ mem, const float* __restrict__ que,
        const float* __restrict__ w_off, const float* __restrict__ b_off) {
    __shared__ float2 sh_x2[3][130];   // rows h-1..h+1, entry i = {x[i-1], x[i]} (zero-padded)
    __shared__ float2 sh_w2[9][28];    // [tap][j] duplicated weights, j=27 is zero pad

    const int bh  = blockIdx.x;
    const int b   = bh >> 7;
    const int h   = bh & 127;
    const int tid = threadIdx.x;
    const int ps  = tid & 15;          // pixel-pair slot: pairs ps, ps+16, ps+32, ps+48
    const int jg  = tid >> 4;          // j-group: j = jg*7 + 0..6

    u64 acc[4][7];
    #pragma unroll
    for (int jj = 0; jj < 7; jj++) {
        int j = jg*7 + jj;
        float bias = (j < JOFF_) ? b_off[j] : 0.f;
        #pragma unroll
        for (int i = 0; i < 4; i++) acc[i][jj] = pack2(bias, bias);
    }
    if (tid < 9) sh_w2[tid][27] = make_float2(0.f, 0.f);

    for (int c = 0; c < CIN_; c++) {
        __syncthreads();   // previous GEMM done before overwriting shared
        const float* xc = (c < CM_) ? (mem + (size_t)(b*CM_ + c)*HW_)
                                    : (que + (size_t)(b*CQ_ + (c - CM_))*HW_);
        // stage input rows (with halo, zero-padded)
        for (int e = tid; e < 390; e += 64) {
            int r = e / 130, i = e - r*130;
            int row = h + r - 1;
            float lo = 0.f, hi = 0.f;
            if (row >= 0 && row < H_) {
                const float* xr = xc + row*W_;
                if (i >= 1 && i <= 128) lo = xr[i-1];
                if (i <= 127)           hi = xr[i];
            }
            sh_x2[r][i] = make_float2(lo, hi);
        }
        // stage duplicated weights for this channel: w_off[j][c][tap]
        for (int e = tid; e < 243; e += 64) {
            int j = e / 9, tap = e - j*9;
            float v = w_off[(j*CIN_ + c)*9 + tap];
            sh_w2[tap][j] = make_float2(v, v);
        }
        __syncthreads();

        #pragma unroll
        for (int tap = 0; tap < 9; tap++) {
            const int ky = tap / 3, kx = tap - ky*3;
            u64 xv[4];
            #pragma unroll
            for (int i = 0; i < 4; i++)
                xv[i] = *(const u64*)&sh_x2[ky][2*(ps + 16*i) + kx];
            u64 wv[7];
            #pragma unroll
            for (int jj = 0; jj < 7; jj++)
                wv[jj] = *(const u64*)&sh_w2[tap][jg*7 + jj];
            #pragma unroll
            for (int i = 0; i < 4; i++)
                #pragma unroll
                for (int jj = 0; jj < 7; jj++)
                    ffma2(acc[i][jj], xv[i], wv[jj]);
        }
    }

    #pragma unroll
    for (int jj = 0; jj < 7; jj++) {
        int j = jg*7 + jj;
        if (j < JOFF_) {
            #pragma unroll
            for (int i = 0; i < 4; i++) {
                u64* dst = (u64*)(g_off + ((size_t)(b*JOFF_ + j)*H_ + h)*W_ + 2*(ps + 16*i));
                *dst = acc[i][jj];
            }
        }
    }
}

// ---------------------------------------------------------------------------
// Deformable conv: out[b][o][h][w] = sum_{k,c} s[k][c][pix] * wt[k][c][o]
// s = mask_k * bilinear(mem_c at grid + tap_k + (dy,dx)), corner weights zeroed OOB.
// Block = one (b,h) row. 128 threads: staging role = 1 pixel each; GEMM role =
// 16 pixel-pair slots x 8 o-groups, each thread 4 pixel-pairs x 8 outputs.
// Per-(pix,k) bilinear coefficients + 4 corner pointers hoisted out of the c-loop.
// ---------------------------------------------------------------------------
__global__ __launch_bounds__(128) void deform_kernel(
        const float* __restrict__ mem, float* __restrict__ out) {
    __shared__ __align__(16) float sh_s[8][W_];   // sampled values, 8 channels x 128 px
    __shared__ float2 sh_w[8][CO_];               // duplicated wt {w,w}

    const int bh  = blockIdx.x;
    const int b   = bh >> 7;
    const int h   = bh & 127;
    const int tid = threadIdx.x;
    const int ps  = tid & 15;
    const int og  = tid >> 4;     // o = og*8 + oo
    const int pix = tid;

    u64 acc[4][8];
    #pragma unroll
    for (int i = 0; i < 4; i++)
        #pragma unroll
        for (int oo = 0; oo < 8; oo++) acc[i][oo] = 0ULL;

    const float* offp = g_off + (size_t)b*JOFF_*HW_ + h*W_ + pix;
    const float* memb = mem + (size_t)b*CM_*HW_;

    for (int k = 0; k < K_; k++) {
        // per-pixel, per-tap sampling setup (staging role)
        float dy  = offp[(2*k)*HW_];
        float dx  = offp[(2*k+1)*HW_];
        float msk = offp[(18+k)*HW_];
        float py = (float)(h + (k/3) - 1) + dy;
        float px = (float)(pix + (k - (k/3)*3) - 1) + dx;
        float y0f = floorf(py), x0f = floorf(px);
        float fy = py - y0f, fx = px - x0f;
        int y0 = (int)y0f, x0 = (int)x0f;
        int y1 = y0 + 1,   x1 = x0 + 1;
        float vy0 = (y0 >= 0 && y0 < H_) ? 1.f : 0.f;
        float vy1 = (y1 >= 0 && y1 < H_) ? 1.f : 0.f;
        float vx0 = (x0 >= 0 && x0 < W_) ? 1.f : 0.f;
        float vx1 = (x1 >= 0 && x1 < W_) ? 1.f : 0.f;
        int y0c = min(max(y0, 0), H_-1), y1c = min(max(y1, 0), H_-1);
        int x0c = min(max(x0, 0), W_-1), x1c = min(max(x1, 0), W_-1);
        float w00 = (1.f-fy)*(1.f-fx)*msk*vy0*vx0;
        float w01 = (1.f-fy)*fx      *msk*vy0*vx1;
        float w10 = fy      *(1.f-fx)*msk*vy1*vx0;
        float w11 = fy      *fx      *msk*vy1*vx1;
        const float* p00 = memb + y0c*W_ + x0c;
        const float* p01 = memb + y0c*W_ + x1c;
        const float* p10 = memb + y1c*W_ + x0c;
        const float* p11 = memb + y1c*W_ + x1c;
        const float* wk  = g_wt + k*CM_*CO_;

        for (int cc0 = 0; cc0 < CM_; cc0 += 8) {
            __syncthreads();   // previous GEMM phase done
            // stage sampled values for 8 channels (immediate c*HW offsets)
            #pragma unroll
            for (int c8 = 0; c8 < 8; c8++) {
                int c = cc0 + c8;
                float s = w00*p00[c*HW_] + w01*p01[c*HW_]
                        + w10*p10[c*HW_] + w11*p11[c*HW_];
                sh_s[c8][pix] = s;
            }
            // stage duplicated weights: 8c x 64o = 512 entries / 128 threads
            #pragma unroll
            for (int e4 = 0; e4 < 4; e4++) {
                int e  = tid + e4*128;
                int c8 = e >> 6, o = e & 63;
                float wv = wk[(cc0 + c8)*CO_ + o];
                sh_w[c8][o] = make_float2(wv, wv);
            }
            __syncthreads();
            // GEMM phase: 8 channels x (4 px-pairs x 8 outputs)
            #pragma unroll
            for (int c8 = 0; c8 < 8; c8++) {
                u64 sv[4];
                #pragma unroll
                for (int i = 0; i < 4; i++)
                    sv[i] = *(const u64*)&sh_s[c8][2*(ps + 16*i)];
                u64 wv[8];
                #pragma unroll
                for (int oo = 0; oo < 8; oo++)
                    wv[oo] = *(const u64*)&sh_w[c8][og*8 + oo];
                #pragma unroll
                for (int i = 0; i < 4; i++)
                    #pragma unroll
                    for (int oo = 0; oo < 8; oo++)
                        ffma2(acc[i][oo], sv[i], wv[oo]);
            }
        }
    }

    #pragma unroll
    for (int oo = 0; oo < 8; oo++) {
        int o = og*8 + oo;
        #pragma unroll
        for (int i = 0; i < 4; i++) {
            u64* dst = (u64*)(out + ((size_t)(b*CO_ + o)*H_ + h)*W_ + 2*(ps + 16*i));
            *dst = acc[i][oo];
        }
    }
}

extern "C" void kernel_launch(void* const* d_in, const int* in_sizes, int n_in,
                              void* d_out, int out_size) {
    const float* mem   = (const float*)d_in[0];
    const float* que   = (const float*)d_in[1];
    const float* w_off = (const float*)d_in[2];
    const float* b_off = (const float*)d_in[3];
    const float* w_def = (const float*)d_in[4];
    float* out = (float*)d_out;

    transpose_wdef_kernel<<<(K_*CM_*CO_ + 255)/256, 256>>>(w_def);
    offset_conv_kernel<<<B_*H_, 64>>>(mem, que, w_off, b_off);
    deform_kernel<<<B_*H_, 128>>>(mem, out);
}

// round 2
// speedup vs baseline: 1.0509x; 1.0509x over previous
#include <cuda_runtime.h>
#include <cstdint>

typedef unsigned long long u64;

#define B_    8
#define CM_   64
#define CQ_   64
#define CIN_  128
#define CO_   64
#define H_    128
#define W_    128
#define K_    9
#define JOFF_ 27
#define HW_   (H_*W_)

// Scratch (no cudaMalloc allowed).
__device__ __align__(16) float  g_off[B_*JOFF_*HW_];      // [b][j][h][w]
__device__ __align__(16) float2 g_wt2[K_*CM_*CO_];        // [k][c][o] duplicated {w,w}
__device__ __align__(16) float2 g_woff2[CIN_*9*28];       // [c][tap][j(28, j=27 zero)] dup {w,w}

__device__ __forceinline__ u64 pack2(float lo, float hi) {
    u64 r; asm("mov.b64 %0, {%1,%2};" : "=l"(r) : "f"(lo), "f"(hi)); return r;
}
__device__ __forceinline__ void ffma2(u64 &d, u64 a, u64 b) {
    asm("fma.rn.f32x2 %0, %1, %2, %0;" : "+l"(d) : "l"(a), "l"(b));
}

// ---------------------------------------------------------------------------
// Prep: transpose+duplicate both weight tensors.
//   g_woff2[c][tap][j] = {w_off[j][c][tap]} x2   (j=27 -> 0)
//   g_wt2  [k][c][o]  = {w_def[o][c][k]} x2
// ---------------------------------------------------------------------------
#define N_WOFF (CIN_*9*28)      // 32256
#define N_WT   (K_*CM_*CO_)     // 36864
__global__ void prep_weights_kernel(const float* __restrict__ w_off,
                                    const float* __restrict__ w_def) {
    int i = blockIdx.x * 256 + threadIdx.x;
    if (i < N_WOFF) {
        int c = i / 252;
        int r = i - c*252;
        int tap = r / 28;
        int j = r - tap*28;
        float v = (j < JOFF_) ? w_off[(j*CIN_ + c)*9 + tap] : 0.f;
        g_woff2[i] = make_float2(v, v);
    } else if (i < N_WOFF + N_WT) {
        int i2 = i - N_WOFF;
        int k = i2 / (CM_*CO_);
        int r = i2 - k*(CM_*CO_);
        int c = r / CO_;
        int o = r - c*CO_;
        float v = w_def[(o*CM_ + c)*K_ + k];
        g_wt2[i2] = make_float2(v, v);
    }
}

// ---------------------------------------------------------------------------
// Offset conv: 2 output rows per block, 128 threads, double-buffered shared,
// one __syncthreads per channel. Thread = (row r2, pixel-pair slot ps, j-group jg).
// ---------------------------------------------------------------------------
__global__ __launch_bounds__(128) void offset_conv_kernel(
        const float* __restrict__ mem, const float* __restrict__ que,
        const float* __restrict__ b_off) {
    __shared__ float2 sx[2][4][130];   // rows h0-1..h0+2; entry i = {x[i-1], x[i]}
    __shared__ float2 sw[2][252];      // [tap*28+j] duplicated weights

    const int bid = blockIdx.x;
    const int b   = bid >> 6;
    const int h0  = (bid & 63) * 2;
    const int tid = threadIdx.x;
    const int r2  = tid >> 6;          // output row within pair
    const int t   = tid & 63;
    const int ps  = t & 15;            // pixel-pair slot (pairs ps, ps+16, ps+32, ps+48)
    const int jg  = t >> 4;            // j = jg*7 + 0..6

    u64 acc[4][7];
    #pragma unroll
    for (int jj = 0; jj < 7; jj++) {
        int j = jg*7 + jj;
        float bias = (j < JOFF_) ? b_off[j] : 0.f;
        #pragma unroll
        for (int i = 0; i < 4; i++) acc[i][jj] = pack2(bias, bias);
    }

    // ---- staging lambda-ish macro via inline code ----
    #define STAGE_OFF(c, p) do {                                              \
        const float* xc = ((c) < CM_) ? (mem + (size_t)(b*CM_ + (c))*HW_)     \
                                      : (que + (size_t)(b*CQ_ + ((c)-CM_))*HW_);\
        for (int e = tid; e < 520; e += 128) {                                \
            int r = e / 130, i = e - r*130;                                   \
            int row = h0 + r - 1;                                             \
            float lo = 0.f, hi = 0.f;                                         \
            if (row >= 0 && row < H_) {                                       \
                const float* xr = xc + row*W_;                                \
                if (i >= 1 && i <= 128) lo = xr[i-1];                         \
                if (i <= 127)           hi = xr[i];                           \
            }                                                                 \
            sx[p][r][i] = make_float2(lo, hi);                                \
        }                                                                     \
        const float2* wsrc = g_woff2 + (c)*252;                               \
        for (int e = tid; e < 252; e += 128) sw[p][e] = wsrc[e];              \
    } while (0)

    STAGE_OFF(0, 0);
    __syncthreads();

    for (int c = 0; c < CIN_; c++) {
        const int p = c & 1;
        if (c + 1 < CIN_) STAGE_OFF(c + 1, p ^ 1);
        // GEMM on buffer p
        #pragma unroll
        for (int tap = 0; tap < 9; tap++) {
            const int ky = tap / 3, kx = tap - ky*3;
            u64 xv[4];
            #pragma unroll
            for (int i = 0; i < 4; i++)
                xv[i] = *(const u64*)&sx[p][r2 + ky][2*(ps + 16*i) + kx];
            u64 wv[7];
            #pragma unroll
            for (int jj = 0; jj < 7; jj++)
                wv[jj] = *(const u64*)&sw[p][tap*28 + jg*7 + jj];
            #pragma unroll
            for (int i = 0; i < 4; i++)
                #pragma unroll
                for (int jj = 0; jj < 7; jj++)
                    ffma2(acc[i][jj], xv[i], wv[jj]);
        }
        __syncthreads();
    }
    #undef STAGE_OFF

    const int h = h0 + r2;
    #pragma unroll
    for (int jj = 0; jj < 7; jj++) {
        int j = jg*7 + jj;
        if (j < JOFF_) {
            #pragma unroll
            for (int i = 0; i < 4; i++) {
                u64* dst = (u64*)(g_off + ((size_t)(b*JOFF_ + j)*H_ + h)*W_ + 2*(ps + 16*i));
                *dst = acc[i][jj];
            }
        }
    }
}

// ---------------------------------------------------------------------------
// Deformable conv: producer/consumer warp specialization, double buffer.
// Block = one (b,h) row, 256 threads: tid<128 consumers (pure LDS+FFMA2 GEMM),
// tid>=128 producers (bilinear sampling + weight copy). 36 chunks of 16 ch.
// ---------------------------------------------------------------------------
#define NCHUNK (K_*4)   // 36

__global__ __launch_bounds__(256) void deform_kernel(
        const float* __restrict__ mem, float* __restrict__ out) {
    __shared__ __align__(16) float  sh_s[2][16][W_];   // sampled, 16 ch x 128 px (16KB)
    __shared__ __align__(16) float2 sh_w[2][16][CO_];  // duplicated weights (16KB)

    const int bh  = blockIdx.x;
    const int b   = bh >> 7;
    const int h   = bh & 127;
    const int tid = threadIdx.x;
    const bool consumer = (tid < 128);

    const float* memb = mem + (size_t)b*CM_*HW_;
    const float* offp = g_off + (size_t)b*JOFF_*HW_ + h*W_ + (tid - 128); // producers only

    // producer staging of chunk q into buffer p
    #define STAGE_DEF(q, p) do {                                              \
        const int k  = (q) >> 2;                                              \
        const int c0 = ((q) & 3) << 4;                                        \
        const int pix = tid - 128;                                            \
        float dy  = offp[(2*k)*HW_];                                          \
        float dx  = offp[(2*k+1)*HW_];                                        \
        float msk = offp[(18+k)*HW_];                                         \
        float py = (float)(h + (k/3) - 1) + dy;                               \
        float px = (float)(pix + (k - (k/3)*3) - 1) + dx;                     \
        float y0f = floorf(py), x0f = floorf(px);                             \
        float fy = py - y0f, fx = px - x0f;                                   \
        int y0 = (int)y0f, x0 = (int)x0f;                                     \
        int y1 = y0 + 1,   x1 = x0 + 1;                                       \
        float vy0 = (y0 >= 0 && y0 < H_) ? 1.f : 0.f;                         \
        float vy1 = (y1 >= 0 && y1 < H_) ? 1.f : 0.f;                         \
        float vx0 = (x0 >= 0 && x0 < W_) ? 1.f : 0.f;                         \
        float vx1 = (x1 >= 0 && x1 < W_) ? 1.f : 0.f;                         \
        int y0c = min(max(y0, 0), H_-1), y1c = min(max(y1, 0), H_-1);         \
        int x0c = min(max(x0, 0), W_-1), x1c = min(max(x1, 0), W_-1);         \
        float w00 = (1.f-fy)*(1.f-fx)*msk*vy0*vx0;                            \
        float w01 = (1.f-fy)*fx      *msk*vy0*vx1;                            \
        float w10 = fy      *(1.f-fx)*msk*vy1*vx0;                            \
        float w11 = fy      *fx      *msk*vy1*vx1;                            \
        const float* p00 = memb + (size_t)(c0*HW_) + y0c*W_ + x0c;            \
        const float* p01 = memb + (size_t)(c0*HW_) + y0c*W_ + x1c;            \
        const float* p10 = memb + (size_t)(c0*HW_) + y1c*W_ + x0c;            \
        const float* p11 = memb + (size_t)(c0*HW_) + y1c*W_ + x1c;            \
        _Pragma("unroll")                                                     \
        for (int c8 = 0; c8 < 16; c8++) {                                     \
            float s = w00*p00[c8*HW_] + w01*p01[c8*HW_]                       \
                    + w10*p10[c8*HW_] + w11*p11[c8*HW_];                      \
            sh_s[p][c8][pix] = s;                                             \
        }                                                                     \
        const uint4* wsrc = (const uint4*)(g_wt2 + (size_t)(k*CM_ + c0)*CO_); \
        uint4* wdst = (uint4*)&sh_w[p][0][0];                                 \
        _Pragma("unroll")                                                     \
        for (int e4 = 0; e4 < 4; e4++)                                        \
            wdst[pix + e4*128] = wsrc[pix + e4*128];                          \
    } while (0)

    u64 acc[4][8];
    int ps = 0, og = 0;
    if (consumer) {
        ps = tid & 15;
        og = tid >> 4;
        #pragma unroll
        for (int i = 0; i < 4; i++)
            #pragma unroll
            for (int oo = 0; oo < 8; oo++) acc[i][oo] = 0ULL;
    } else {
        STAGE_DEF(0, 0);
    }
    __syncthreads();

    for (int q = 0; q < NCHUNK; q++) {
        const int p = q & 1;
        if (consumer) {
            #pragma unroll
            for (int c8 = 0; c8 < 16; c8++) {
                u64 sv[4];
                #pragma unroll
                for (int i = 0; i < 4; i++)
                    sv[i] = *(const u64*)&sh_s[p][c8][2*(ps + 16*i)];
                u64 wv[8];
                #pragma unroll
                for (int oo = 0; oo < 8; oo++)
                    wv[oo] = *(const u64*)&sh_w[p][c8][og*8 + oo];
                #pragma unroll
                for (int i = 0; i < 4; i++)
                    #pragma unroll
                    for (int oo = 0; oo < 8; oo++)
                        ffma2(acc[i][oo], sv[i], wv[oo]);
            }
        } else {
            if (q + 1 < NCHUNK) STAGE_DEF(q + 1, p ^ 1);
        }
        __syncthreads();
    }
    #undef STAGE_DEF

    if (consumer) {
        #pragma unroll
        for (int oo = 0; oo < 8; oo++) {
            int o = og*8 + oo;
            #pragma unroll
            for (int i = 0; i < 4; i++) {
                u64* dst = (u64*)(out + ((size_t)(b*CO_ + o)*H_ + h)*W_ + 2*(ps + 16*i));
                *dst = acc[i][oo];
            }
        }
    }
}

extern "C" void kernel_launch(void* const* d_in, const int* in_sizes, int n_in,
                              void* d_out, int out_size) {
    const float* mem   = (const float*)d_in[0];
    const float* que   = (const float*)d_in[1];
    const float* w_off = (const float*)d_in[2];
    const float* b_off = (const float*)d_in[3];
    const float* w_def = (const float*)d_in[4];
    float* out = (float*)d_out;

    prep_weights_kernel<<<(N_WOFF + N_WT + 255)/256, 256>>>(w_off, w_def);
    offset_conv_kernel<<<B_*H_/2, 128>>>(mem, que, b_off);
    deform_kernel<<<B_*H_, 256>>>(mem, out);
}

// round 4
// speedup vs baseline: 1.2677x; 1.2063x over previous
#include <cuda_runtime.h>
#include <cstdint>

typedef unsigned long long u64;

#define B_    8
#define CM_   64
#define CQ_   64
#define CIN_  128
#define CO_   64
#define H_    128
#define W_    128
#define K_    9
#define JOFF_ 27
#define HW_   (H_*W_)

// Scratch (no cudaMalloc allowed).
__device__ __align__(16) float  g_off[B_*JOFF_*HW_];      // [b][j][h][w]
__device__ __align__(16) float2 g_wt2[K_*CM_*CO_];        // [k][c][o] duplicated {w,w}
__device__ __align__(16) float2 g_woff2[CIN_*9*28];       // [c][tap][j(28, j=27 zero)] dup {w,w}

__device__ __forceinline__ u64 pack2(float lo, float hi) {
    u64 r; asm("mov.b64 %0, {%1,%2};" : "=l"(r) : "f"(lo), "f"(hi)); return r;
}
__device__ __forceinline__ void ffma2(u64 &d, u64 a, u64 b) {
    asm("fma.rn.f32x2 %0, %1, %2, %0;" : "+l"(d) : "l"(a), "l"(b));
}

// ---------------------------------------------------------------------------
// Prep: transpose+duplicate both weight tensors.
// ---------------------------------------------------------------------------
#define N_WOFF (CIN_*9*28)      // 32256
#define N_WT   (K_*CM_*CO_)     // 36864
__global__ void prep_weights_kernel(const float* __restrict__ w_off,
                                    const float* __restrict__ w_def) {
    int i = blockIdx.x * 256 + threadIdx.x;
    if (i < N_WOFF) {
        int c = i / 252;
        int r = i - c*252;
        int tap = r / 28;
        int j = r - tap*28;
        float v = (j < JOFF_) ? w_off[(j*CIN_ + c)*9 + tap] : 0.f;
        g_woff2[i] = make_float2(v, v);
    } else if (i < N_WOFF + N_WT) {
        int i2 = i - N_WOFF;
        int k = i2 / (CM_*CO_);
        int r = i2 - k*(CM_*CO_);
        int c = r / CO_;
        int o = r - c*CO_;
        float v = w_def[(o*CM_ + c)*K_ + k];
        g_wt2[i2] = make_float2(v, v);
    }
}

// ---------------------------------------------------------------------------
// Offset conv: 2 output rows per block, 128 threads, double-buffered shared.
// TRUE software pipeline: LDG(c+1)->regs issued BEFORE GEMM(c); regs->STS
// AFTER GEMM(c); one sync per channel. LDG latency hides under 250+ FFMA2s.
// ---------------------------------------------------------------------------
__global__ __launch_bounds__(128) void offset_conv_kernel(
        const float* __restrict__ mem, const float* __restrict__ que,
        const float* __restrict__ b_off) {
    __shared__ float2 sx[2][4][130];   // rows h0-1..h0+2; entry i = {x[i-1], x[i]}
    __shared__ float2 sw[2][252];      // [tap*28+j] duplicated weights

    const int bid = blockIdx.x;
    const int b   = bid >> 6;
    const int h0  = (bid & 63) * 2;
    const int tid = threadIdx.x;
    const int r2  = tid >> 6;          // output row within pair
    const int t   = tid & 63;
    const int ps  = t & 15;            // pixel-pair slot (pairs ps, ps+16, ps+32, ps+48)
    const int jg  = t >> 4;            // j = jg*7 + 0..6

    u64 acc[4][7];
    #pragma unroll
    for (int jj = 0; jj < 7; jj++) {
        int j = jg*7 + jj;
        float bias = (j < JOFF_) ? b_off[j] : 0.f;
        #pragma unroll
        for (int i = 0; i < 4; i++) acc[i][jj] = pack2(bias, bias);
    }

    float2 xreg[5];   // staged input entries (520 total / 128 threads)
    float2 wreg[2];   // staged weight entries (252 total / 128 threads)

    #define LOAD_REGS(c) do {                                                 \
        const float* xc = ((c) < CM_) ? (mem + (size_t)(b*CM_ + (c))*HW_)     \
                                      : (que + (size_t)(b*CQ_ + ((c)-CM_))*HW_);\
        _Pragma("unroll")                                                     \
        for (int s = 0; s < 5; s++) {                                         \
            int e = tid + 128*s;                                              \
            float lo = 0.f, hi = 0.f;                                         \
            if (e < 520) {                                                    \
                int r = e / 130, i = e - r*130;                               \
                int row = h0 + r - 1;                                         \
                if (row >= 0 && row < H_) {                                   \
                    const float* xr = xc + row*W_;                            \
                    if (i >= 1 && i <= 128) lo = xr[i-1];                     \
                    if (i <= 127)           hi = xr[i];                       \
                }                                                             \
            }                                                                 \
            xreg[s] = make_float2(lo, hi);                                    \
        }                                                                     \
        const float2* wsrc = g_woff2 + (c)*252;                               \
        _Pragma("unroll")                                                     \
        for (int s = 0; s < 2; s++) {                                         \
            int e = tid + 128*s;                                              \
            wreg[s] = (e < 252) ? wsrc[e] : make_float2(0.f, 0.f);            \
        }                                                                     \
    } while (0)

    #define STORE_REGS(p) do {                                                \
        _Pragma("unroll")                                                     \
        for (int s = 0; s < 5; s++) {                                         \
            int e = tid + 128*s;                                              \
            if (e < 520) { int r = e / 130, i = e - r*130; sx[p][r][i] = xreg[s]; } \
        }                                                                     \
        _Pragma("unroll")                                                     \
        for (int s = 0; s < 2; s++) {                                         \
            int e = tid + 128*s;                                              \
            if (e < 252) sw[p][e] = wreg[s];                                  \
        }                                                                     \
    } while (0)

    LOAD_REGS(0);
    STORE_REGS(0);
    __syncthreads();

    for (int c = 0; c < CIN_; c++) {
        const int p = c & 1;
        if (c + 1 < CIN_) LOAD_REGS(c + 1);        // LDGs in flight under GEMM
        // GEMM on buffer p
        #pragma unroll
        for (int tap = 0; tap < 9; tap++) {
            const int ky = tap / 3, kx = tap - ky*3;
            u64 xv[4];
            #pragma unroll
            for (int i = 0; i < 4; i++)
                xv[i] = *(const u64*)&sx[p][r2 + ky][2*(ps + 16*i) + kx];
            u64 wv[7];
            #pragma unroll
            for (int jj = 0; jj < 7; jj++)
                wv[jj] = *(const u64*)&sw[p][tap*28 + jg*7 + jj];
            #pragma unroll
            for (int i = 0; i < 4; i++)
                #pragma unroll
                for (int jj = 0; jj < 7; jj++)
                    ffma2(acc[i][jj], xv[i], wv[jj]);
        }
        if (c + 1 < CIN_) STORE_REGS(p ^ 1);       // LDG results consumed here
        __syncthreads();
    }
    #undef LOAD_REGS
    #undef STORE_REGS

    const int h = h0 + r2;
    #pragma unroll
    for (int jj = 0; jj < 7; jj++) {
        int j = jg*7 + jj;
        if (j < JOFF_) {
            #pragma unroll
            for (int i = 0; i < 4; i++) {
                u64* dst = (u64*)(g_off + ((size_t)(b*JOFF_ + j)*H_ + h)*W_ + 2*(ps + 16*i));
                *dst = acc[i][jj];
            }
        }
    }
}

// ---------------------------------------------------------------------------
// Deformable conv: producer/consumer warp specialization, double buffer.
// Block = one (b,h) row, 256 threads: tid<128 consumers (pure LDS+FFMA2 GEMM),
// tid>=128 producers (bilinear sampling + weight copy). 36 chunks of 16 ch.
// ---------------------------------------------------------------------------
#define NCHUNK (K_*4)   // 36

__global__ __launch_bounds__(256) void deform_kernel(
        const float* __restrict__ mem, float* __restrict__ out) {
    __shared__ __align__(16) float  sh_s[2][16][W_];   // sampled, 16 ch x 128 px (16KB)
    __shared__ __align__(16) float2 sh_w[2][16][CO_];  // duplicated weights (16KB)

    const int bh  = blockIdx.x;
    const int b   = bh >> 7;
    const int h   = bh & 127;
    const int tid = threadIdx.x;
    const bool consumer = (tid < 128);

    const float* memb = mem + (size_t)b*CM_*HW_;
    const float* offp = g_off + (size_t)b*JOFF_*HW_ + h*W_ + (tid - 128); // producers only

    #define STAGE_DEF(q, p) do {                                              \
        const int k  = (q) >> 2;                                              \
        const int c0 = ((q) & 3) << 4;                                        \
        const int pix = tid - 128;                                            \
        float dy  = offp[(2*k)*HW_];                                          \
        float dx  = offp[(2*k+1)*HW_];                                        \
        float msk = offp[(18+k)*HW_];                                         \
        float py = (float)(h + (k/3) - 1) + dy;                               \
        float px = (float)(pix + (k - (k/3)*3) - 1) + dx;                     \
        float y0f = floorf(py), x0f = floorf(px);                             \
        float fy = py - y0f, fx = px - x0f;                                   \
        int y0 = (int)y0f, x0 = (int)x0f;                                     \
        int y1 = y0 + 1,   x1 = x0 + 1;                                       \
        float vy0 = (y0 >= 0 && y0 < H_) ? 1.f : 0.f;                         \
        float vy1 = (y1 >= 0 && y1 < H_) ? 1.f : 0.f;                         \
        float vx0 = (x0 >= 0 && x0 < W_) ? 1.f : 0.f;                         \
        float vx1 = (x1 >= 0 && x1 < W_) ? 1.f : 0.f;                         \
        int y0c = min(max(y0, 0), H_-1), y1c = min(max(y1, 0), H_-1);         \
        int x0c = min(max(x0, 0), W_-1), x1c = min(max(x1, 0), W_-1);         \
        float w00 = (1.f-fy)*(1.f-fx)*msk*vy0*vx0;                            \
        float w01 = (1.f-fy)*fx      *msk*vy0*vx1;                            \
        float w10 = fy      *(1.f-fx)*msk*vy1*vx0;                            \
        float w11 = fy      *fx      *msk*vy1*vx1;                            \
        const float* p00 = memb + (size_t)(c0*HW_) + y0c*W_ + x0c;            \
        const float* p01 = memb + (size_t)(c0*HW_) + y0c*W_ + x1c;            \
        const float* p10 = memb + (size_t)(c0*HW_) + y1c*W_ + x0c;            \
        const float* p11 = memb + (size_t)(c0*HW_) + y1c*W_ + x1c;            \
        _Pragma("unroll")                                                     \
        for (int c8 = 0; c8 < 16; c8++) {                                     \
            float s = w00*p00[c8*HW_] + w01*p01[c8*HW_]                       \
                    + w10*p10[c8*HW_] + w11*p11[c8*HW_];                      \
            sh_s[p][c8][pix] = s;                                             \
        }                                                                     \
        const uint4* wsrc = (const uint4*)(g_wt2 + (size_t)(k*CM_ + c0)*CO_); \
        uint4* wdst = (uint4*)&sh_w[p][0][0];                                 \
        _Pragma("unroll")                                                     \
        for (int e4 = 0; e4 < 4; e4++)                                        \
            wdst[pix + e4*128] = wsrc[pix + e4*128];                          \
    } while (0)

    u64 acc[4][8];
    int ps = 0, og = 0;
    if (consumer) {
        ps = tid & 15;
        og = tid >> 4;
        #pragma unroll
        for (int i = 0; i < 4; i++)
            #pragma unroll
            for (int oo = 0; oo < 8; oo++) acc[i][oo] = 0ULL;
    } else {
        STAGE_DEF(0, 0);
    }
    __syncthreads();

    for (int q = 0; q < NCHUNK; q++) {
        const int p = q & 1;
        if (consumer) {
            #pragma unroll
            for (int c8 = 0; c8 < 16; c8++) {
                u64 sv[4];
                #pragma unroll
                for (int i = 0; i < 4; i++)
                    sv[i] = *(const u64*)&sh_s[p][c8][2*(ps + 16*i)];
                u64 wv[8];
                #pragma unroll
                for (int oo = 0; oo < 8; oo++)
                    wv[oo] = *(const u64*)&sh_w[p][c8][og*8 + oo];
                #pragma unroll
                for (int i = 0; i < 4; i++)
                    #pragma unroll
                    for (int oo = 0; oo < 8; oo++)
                        ffma2(acc[i][oo], sv[i], wv[oo]);
            }
        } else {
            if (q + 1 < NCHUNK) STAGE_DEF(q + 1, p ^ 1);
        }
        __syncthreads();
    }
    #undef STAGE_DEF

    if (consumer) {
        #pragma unroll
        for (int oo = 0; oo < 8; oo++) {
            int o = og*8 + oo;
            #pragma unroll
            for (int i = 0; i < 4; i++) {
                u64* dst = (u64*)(out + ((size_t)(b*CO_ + o)*H_ + h)*W_ + 2*(ps + 16*i));
                *dst = acc[i][oo];
            }
        }
    }
}

extern "C" void kernel_launch(void* const* d_in, const int* in_sizes, int n_in,
                              void* d_out, int out_size) {
    const float* mem   = (const float*)d_in[0];
    const float* que   = (const float*)d_in[1];
    const float* w_off = (const float*)d_in[2];
    const float* b_off = (const float*)d_in[3];
    const float* w_def = (const float*)d_in[4];
    float* out = (float*)d_out;

    prep_weights_kernel<<<(N_WOFF + N_WT + 255)/256, 256>>>(w_off, w_def);
    offset_conv_kernel<<<B_*H_/2, 128>>>(mem, que, b_off);
    deform_kernel<<<B_*H_, 256>>>(mem, out);
}

// round 5
// speedup vs baseline: 1.4366x; 1.1332x over previous
#include <cuda_runtime.h>
#include <cstdint>

typedef unsigned long long u64;

#define B_    8
#define CM_   64
#define CQ_   64
#define CIN_  128
#define CO_   64
#define H_    128
#define W_    128
#define K_    9
#define JOFF_ 27
#define HW_   (H_*W_)

// Scratch (no cudaMalloc allowed).
__device__ __align__(16) float  g_off[B_*JOFF_*HW_];      // [b][j][h][w]
__device__ __align__(16) float2 g_wt2[K_*CM_*CO_];        // [k][c][o] duplicated {w,w}
__device__ __align__(16) float2 g_woff2[CIN_*9*32];       // [c][tap][slot32] dup {w,w}, slot=jg*8+jj (jj<7 valid)

__device__ __forceinline__ u64 pack2(float lo, float hi) {
    u64 r; asm("mov.b64 %0, {%1,%2};" : "=l"(r) : "f"(lo), "f"(hi)); return r;
}
__device__ __forceinline__ void ffma2(u64 &d, u64 a, u64 b) {
    asm("fma.rn.f32x2 %0, %1, %2, %0;" : "+l"(d) : "l"(a), "l"(b));
}

union W4 { float4 f; u64 d[2]; };   // {w0,w0,w1,w1} -> two ready f32x2 operands

// ---------------------------------------------------------------------------
// Prep: transpose+duplicate both weight tensors.
// ---------------------------------------------------------------------------
#define N_WOFF (CIN_*9*32)      // 36864
#define N_WT   (K_*CM_*CO_)     // 36864
__global__ void prep_weights_kernel(const float* __restrict__ w_off,
                                    const float* __restrict__ w_def) {
    int i = blockIdx.x * 256 + threadIdx.x;
    if (i < N_WOFF) {
        int c = i / 288;
        int r = i - c*288;
        int tap = r / 32;
        int s = r & 31;
        int jg = s >> 3, jj = s & 7;
        int j = jg*7 + jj;
        float v = (jj < 7 && j < JOFF_) ? w_off[(j*CIN_ + c)*9 + tap] : 0.f;
        g_woff2[i] = make_float2(v, v);
    } else if (i < N_WOFF + N_WT) {
        int i2 = i - N_WOFF;
        int k = i2 / (CM_*CO_);
        int r = i2 - k*(CM_*CO_);
        int c = r / CO_;
        int o = r - c*CO_;
        float v = w_def[(o*CM_ + c)*K_ + k];
        g_wt2[i2] = make_float2(v, v);
    }
}

// ---------------------------------------------------------------------------
// Offset conv: 2 output rows per block, 128 threads, double-buffered shared,
// reg-staged software pipeline (LDG under GEMM). Weights via LDS.128 pairs.
// ---------------------------------------------------------------------------
__global__ __launch_bounds__(128) void offset_conv_kernel(
        const float* __restrict__ mem, const float* __restrict__ que,
        const float* __restrict__ b_off) {
    __shared__ float2 sx[2][4][130];            // rows h0-1..h0+2; entry i = {x[i-1], x[i]}
    __shared__ __align__(16) float2 sw[2][9][32]; // [tap][slot] duplicated weights

    const int bid = blockIdx.x;
    const int b   = bid >> 6;
    const int h0  = (bid & 63) * 2;
    const int tid = threadIdx.x;
    const int r2  = tid >> 6;          // output row within pair
    const int t   = tid & 63;
    const int ps  = t & 15;            // pixel-pair slot (pairs ps, ps+16, ps+32, ps+48)
    const int jg  = t >> 4;            // j = jg*7 + 0..6

    u64 acc[4][7];
    #pragma unroll
    for (int jj = 0; jj < 7; jj++) {
        int j = jg*7 + jj;
        float bias = (j < JOFF_) ? b_off[j] : 0.f;
        #pragma unroll
        for (int i = 0; i < 4; i++) acc[i][jj] = pack2(bias, bias);
    }

    float2 xreg[5];   // staged input entries (520 total / 128 threads)
    float2 wreg[3];   // staged weight entries (288 total / 128 threads)

    #define LOAD_REGS(c) do {                                                 \
        const float* xc = ((c) < CM_) ? (mem + (size_t)(b*CM_ + (c))*HW_)     \
                                      : (que + (size_t)(b*CQ_ + ((c)-CM_))*HW_);\
        _Pragma("unroll")                                                     \
        for (int s = 0; s < 5; s++) {                                         \
            int e = tid + 128*s;                                              \
            float lo = 0.f, hi = 0.f;                                         \
            if (e < 520) {                                                    \
                int r = e / 130, i = e - r*130;                               \
                int row = h0 + r - 1;                                         \
                if (row >= 0 && row < H_) {                                   \
                    const float* xr = xc + row*W_;                            \
                    if (i >= 1 && i <= 128) lo = xr[i-1];                     \
                    if (i <= 127)           hi = xr[i];                       \
                }                                                             \
            }                                                                 \
            xreg[s] = make_float2(lo, hi);                                    \
        }                                                                     \
        const float2* wsrc = g_woff2 + (size_t)(c)*288;                       \
        _Pragma("unroll")                                                     \
        for (int s = 0; s < 3; s++) {                                         \
            int e = tid + 128*s;                                              \
            wreg[s] = (e < 288) ? wsrc[e] : make_float2(0.f, 0.f);            \
        }                                                                     \
    } while (0)

    #define STORE_REGS(p) do {                                                \
        _Pragma("unroll")                                                     \
        for (int s = 0; s < 5; s++) {                                         \
            int e = tid + 128*s;                                              \
            if (e < 520) { int r = e / 130, i = e - r*130; sx[p][r][i] = xreg[s]; } \
        }                                                                     \
        _Pragma("unroll")                                                     \
        for (int s = 0; s < 3; s++) {                                         \
            int e = tid + 128*s;                                              \
            if (e < 288) { int tp = e >> 5; sw[p][tp][e & 31] = wreg[s]; }    \
        }                                                                     \
    } while (0)

    LOAD_REGS(0);
    STORE_REGS(0);
    __syncthreads();

    for (int c = 0; c < CIN_; c++) {
        const int p = c & 1;
        if (c + 1 < CIN_) LOAD_REGS(c + 1);        // LDGs in flight under GEMM
        #pragma unroll
        for (int tap = 0; tap < 9; tap++) {
            const int ky = tap / 3, kx = tap - ky*3;
            u64 xv[4];
            #pragma unroll
            for (int i = 0; i < 4; i++)
                xv[i] = *(const u64*)&sx[p][r2 + ky][2*(ps + 16*i) + kx];
            W4 wq[4];
            #pragma unroll
            for (int m = 0; m < 4; m++)
                wq[m].f = *(const float4*)&sw[p][tap][jg*8 + 2*m];
            #pragma unroll
            for (int i = 0; i < 4; i++)
                #pragma unroll
                for (int m = 0; m < 4; m++) {
                    ffma2(acc[i][2*m], xv[i], wq[m].d[0]);
                    if (m < 3) ffma2(acc[i][2*m+1], xv[i], wq[m].d[1]);
                }
        }
        if (c + 1 < CIN_) STORE_REGS(p ^ 1);       // LDG results consumed here
        __syncthreads();
    }
    #undef LOAD_REGS
    #undef STORE_REGS

    const int h = h0 + r2;
    #pragma unroll
    for (int jj = 0; jj < 7; jj++) {
        int j = jg*7 + jj;
        if (j < JOFF_) {
            #pragma unroll
            for (int i = 0; i < 4; i++) {
                u64* dst = (u64*)(g_off + ((size_t)(b*JOFF_ + j)*H_ + h)*W_ + 2*(ps + 16*i));
                *dst = acc[i][jj];
            }
        }
    }
}

// ---------------------------------------------------------------------------
// Deformable conv: producer/consumer warp specialization, double buffer.
// Block = 2 (b,h) rows, 256 threads: tid<128 consumers (8 px-pairs x 8 outs,
// pure LDS+FFMA2), tid>=128 producers (bilinear sampling for both rows +
// weight copy). 36 chunks of 16 channels. sh_s row stride 144 (==16 mod 32)
// makes consumer sv LDS.64 exactly conflict-free; weights via LDS.128.
// ---------------------------------------------------------------------------
#define NCHUNK (K_*4)   // 36
#define SROW   144

__global__ __launch_bounds__(256) void deform_kernel(
        const float* __restrict__ mem, float* __restrict__ out) {
    __shared__ __align__(16) float  sh_s[2][16][2*SROW];  // [buf][c8][r*SROW+pix] (36.9KB)
    __shared__ __align__(16) float2 sh_w[2][16][CO_];     // duplicated weights (16KB)

    const int bid = blockIdx.x;
    const int b   = bid >> 6;
    const int h0  = (bid & 63) * 2;
    const int tid = threadIdx.x;
    const bool consumer = (tid < 128);

    const float* memb = mem + (size_t)b*CM_*HW_;

    // producer staging of chunk q into buffer p (both rows)
    #define STAGE_DEF(q, p) do {                                              \
        const int k  = (q) >> 2;                                              \
        const int c0 = ((q) & 3) << 4;                                        \
        const int pix = tid - 128;                                            \
        _Pragma("unroll")                                                     \
        for (int r = 0; r < 2; r++) {                                         \
            const int hr = h0 + r;                                            \
            const float* offp = g_off + (size_t)b*JOFF_*HW_ + hr*W_ + pix;    \
            float dy  = offp[(2*k)*HW_];                                      \
            float dx  = offp[(2*k+1)*HW_];                                    \
            float msk = offp[(18+k)*HW_];                                     \
            float py = (float)(hr + (k/3) - 1) + dy;                          \
            float px = (float)(pix + (k - (k/3)*3) - 1) + dx;                 \
            float y0f = floorf(py), x0f = floorf(px);                         \
            float fy = py - y0f, fx = px - x0f;                               \
            int y0 = (int)y0f, x0 = (int)x0f;                                 \
            int y1 = y0 + 1,   x1 = x0 + 1;                                   \
            float vy0 = (y0 >= 0 && y0 < H_) ? 1.f : 0.f;                     \
            float vy1 = (y1 >= 0 && y1 < H_) ? 1.f : 0.f;                     \
            float vx0 = (x0 >= 0 && x0 < W_) ? 1.f : 0.f;                     \
            float vx1 = (x1 >= 0 && x1 < W_) ? 1.f : 0.f;                     \
            int y0c = min(max(y0, 0), H_-1), y1c = min(max(y1, 0), H_-1);     \
            int x0c = min(max(x0, 0), W_-1), x1c = min(max(x1, 0), W_-1);     \
            float w00 = (1.f-fy)*(1.f-fx)*msk*vy0*vx0;                        \
            float w01 = (1.f-fy)*fx      *msk*vy0*vx1;                        \
            float w10 = fy      *(1.f-fx)*msk*vy1*vx0;                        \
            float w11 = fy      *fx      *msk*vy1*vx1;                        \
            const float* p00 = memb + (size_t)(c0*HW_) + y0c*W_ + x0c;        \
            const float* p01 = memb + (size_t)(c0*HW_) + y0c*W_ + x1c;        \
            const float* p10 = memb + (size_t)(c0*HW_) + y1c*W_ + x0c;        \
            const float* p11 = memb + (size_t)(c0*HW_) + y1c*W_ + x1c;        \
            _Pragma("unroll")                                                 \
            for (int c8 = 0; c8 < 16; c8++) {                                 \
                float s = w00*p00[c8*HW_] + w01*p01[c8*HW_]                   \
                        + w10*p10[c8*HW_] + w11*p11[c8*HW_];                  \
                sh_s[p][c8][r*SROW + pix] = s;                                \
            }                                                                 \
        }                                                                     \
        const uint4* wsrc = (const uint4*)(g_wt2 + (size_t)(k*CM_ + c0)*CO_); \
        uint4* wdst = (uint4*)&sh_w[p][0][0];                                 \
        {                                                                     \
            const int pix2 = tid - 128;                                       \
            _Pragma("unroll")                                                 \
            for (int e4 = 0; e4 < 4; e4++)                                    \
                wdst[pix2 + e4*128] = wsrc[pix2 + e4*128];                    \
        }                                                                     \
    } while (0)

    u64 acc[8][8];
    int psg = 0, og = 0, rr = 0;
    if (consumer) {
        og  = tid >> 4;          // output group: o = og*8 + oo
        rr  = (tid >> 3) & 1;    // row within pair
        psg = tid & 7;           // px-pair = psg + 8*i, i=0..7
        #pragma unroll
        for (int i = 0; i < 8; i++)
            #pragma unroll
            for (int oo = 0; oo < 8; oo++) acc[i][oo] = 0ULL;
    } else {
        STAGE_DEF(0, 0);
    }
    __syncthreads();

    for (int q = 0; q < NCHUNK; q++) {
        const int p = q & 1;
        if (consumer) {
            #pragma unroll
            for (int c8 = 0; c8 < 16; c8++) {
                u64 sv[8];
                #pragma unroll
                for (int i = 0; i < 8; i++)
                    sv[i] = *(const u64*)&sh_s[p][c8][rr*SROW + 2*(psg + 8*i)];
                W4 wq[4];
                #pragma unroll
                for (int m = 0; m < 4; m++)
                    wq[m].f = *(const float4*)&sh_w[p][c8][og*8 + 2*m];
                #pragma unroll
                for (int i = 0; i < 8; i++)
                    #pragma unroll
                    for (int m = 0; m < 4; m++) {
                        ffma2(acc[i][2*m],   sv[i], wq[m].d[0]);
                        ffma2(acc[i][2*m+1], sv[i], wq[m].d[1]);
                    }
            }
        } else {
            if (q + 1 < NCHUNK) STAGE_DEF(q + 1, p ^ 1);
        }
        __syncthreads();
    }
    #undef STAGE_DEF

    if (consumer) {
        const int h = h0 + rr;
        #pragma unroll
        for (int oo = 0; oo < 8; oo++) {
            int o = og*8 + oo;
            #pragma unroll
            for (int i = 0; i < 8; i++) {
                u64* dst = (u64*)(out + ((size_t)(b*CO_ + o)*H_ + h)*W_ + 2*(psg + 8*i));
                *dst = acc[i][oo];
            }
        }
    }
}

extern "C" void kernel_launch(void* const* d_in, const int* in_sizes, int n_in,
                              void* d_out, int out_size) {
    const float* mem   = (const float*)d_in[0];
    const float* que   = (const float*)d_in[1];
    const float* w_off = (const float*)d_in[2];
    const float* b_off = (const float*)d_in[3];
    const float* w_def = (const float*)d_in[4];
    float* out = (float*)d_out;

    prep_weights_kernel<<<(N_WOFF + N_WT + 255)/256, 256>>>(w_off, w_def);
    offset_conv_kernel<<<B_*H_/2, 128>>>(mem, que, b_off);
    deform_kernel<<<B_*H_/2, 256>>>(mem, out);
}